// round 7
// baseline (speedup 1.0000x reference)
#include <cuda_runtime.h>
#include <cuda_fp16.h>
#include <cstdint>
#include <math.h>

constexpr int kT = 4, kB = 8, kC = 384, kN = 1024;
constexpr int kBCN  = kB * kC * kN;
constexpr int kTBCN = kT * kBCN;            // 12,582,912
constexpr float kEPS = 1e-5f;
constexpr int kWelems = kC * kC;            // 147456
constexpr float kLoScale = 1.0f / 4096.0f;

// ---------------- device scratch ----------------
__device__ __half g_wqkv[6 * kWelems];      // [branch*2+split][m][k]  (hi, lo*4096)
__device__ __half g_wp[2 * kWelems];        // [split][m][k]
__device__ __half g_sx[kTBCN];              // input spikes  [t][b][n][c]
__device__ __half g_qb[kTBCN];              // q spikes      [t][b][n][c]
__device__ __half g_kb[kTBCN];              // k spikes      [t][b][c][n]
__device__ __half g_vb[kTBCN];              // v spikes      [t][b][c][n]
__device__ float g_kvsum[kT * kB * kC];
__device__ __half g_kvsh[kT * kB * kC];     // kv spikes (fp16)

// ---------------- helpers ----------------
__device__ __forceinline__ uint32_t smem_u32(const void* p) {
    uint32_t a;
    asm("{ .reg .u64 t; cvta.to.shared.u64 t, %1; cvt.u32.u64 %0, t; }" : "=r"(a) : "l"(p));
    return a;
}
__device__ __forceinline__ void cp16(uint32_t dst, const void* src) {
    asm volatile("cp.async.cg.shared.global [%0], [%1], 16;" :: "r"(dst), "l"(src));
}
__device__ __forceinline__ void ldm_x4(uint32_t* r, uint32_t addr) {
    asm volatile("ldmatrix.sync.aligned.m8n8.x4.shared.b16 {%0,%1,%2,%3}, [%4];"
                 : "=r"(r[0]), "=r"(r[1]), "=r"(r[2]), "=r"(r[3]) : "r"(addr));
}
__device__ __forceinline__ void mma16816(float* c, const uint32_t* a, uint32_t b0, uint32_t b1) {
    asm volatile("mma.sync.aligned.m16n8k16.row.col.f32.f16.f16.f32 "
                 "{%0,%1,%2,%3}, {%4,%5,%6,%7}, {%8,%9}, {%0,%1,%2,%3};"
                 : "+f"(c[0]), "+f"(c[1]), "+f"(c[2]), "+f"(c[3])
                 : "r"(a[0]), "r"(a[1]), "r"(a[2]), "r"(a[3]), "r"(b0), "r"(b1));
}
__device__ __forceinline__ uint32_t hmul2u(uint32_t a, uint32_t b) {
    __half2 r = __hmul2(*(__half2*)&a, *(__half2*)&b);
    return *(uint32_t*)&r;
}

// GEMM tiling: 128(M) x 64(N) x 32(K), 8 warps (4m x 2n), dual-split accumulation.
constexpr int BM = 128, BN = 64, BK = 32;
constexpr int PITCH = 40;                        // half elems per smem row (80B)
constexpr int A_ELEMS = 2 * BM * PITCH;          // 10240 (2 splits)
constexpr int B_ELEMS = BN * PITCH;              // 2560
constexpr int STAGE_ELEMS = A_ELEMS + B_ELEMS;   // 12800
constexpr int STAGE_BYTES = STAGE_ELEMS * 2;     // 25600
// fused kernel smem: 2 stages + LIF-state (256 threads x 32 floats)
constexpr int VST_OFF  = 2 * STAGE_BYTES;        // 51200
constexpr int FSMEM    = VST_OFF + 256 * 32 * 4; // 83968
// q staging aliases stage 1 (dead after last chunk): 64 rows x 136 halves
constexpr int QPITCH = 136;

// proj kernel smem: 2 stages only
constexpr int SMEM_BYTES = 2 * STAGE_BYTES;      // 51200

// ---------------------------------------------------------------------------
// K0: split fp32 weights into (hi, lo*4096) fp16 pair.
// ---------------------------------------------------------------------------
__global__ void split_w_kernel(const float* __restrict__ qw, const float* __restrict__ kw,
                               const float* __restrict__ vw, const float* __restrict__ pw) {
    int idx = blockIdx.x * 256 + threadIdx.x;
    if (idx >= 4 * kWelems) return;
    int mat = idx / kWelems;
    int e = idx - mat * kWelems;
    const float* src = (mat == 0) ? qw : (mat == 1) ? kw : (mat == 2) ? vw : pw;
    float w = src[e];
    __half h = __float2half_rn(w);
    __half l = __float2half_rn((w - __half2float(h)) * 4096.0f);
    if (mat < 3) {
        g_wqkv[(mat * 2 + 0) * kWelems + e] = h;
        g_wqkv[(mat * 2 + 1) * kWelems + e] = l;
    } else {
        g_wp[0 * kWelems + e] = h;
        g_wp[1 * kWelems + e] = l;
    }
}

// ---------------------------------------------------------------------------
// K1: LIF on x [t][b][c][n] -> fp16 spikes transposed to [t][b][n][c].
// ---------------------------------------------------------------------------
__global__ void lif_x_kernel(const float* __restrict__ x) {
    __shared__ __half sm[32][36];
    const int lane = threadIdx.x & 31, wid = threadIdx.x >> 5;
    const int n0 = blockIdx.x * 32, c0 = blockIdx.y * 32, b = blockIdx.z;
    float v[4] = {0.f, 0.f, 0.f, 0.f};
    for (int t = 0; t < kT; t++) {
#pragma unroll
        for (int j = 0; j < 4; j++) {
            int c = c0 + wid * 4 + j;
            float xv = x[((size_t)((t * kB + b) * kC + c)) * kN + n0 + lane];
            v[j] += (xv - v[j]) * 0.5f;
            float s = 0.f;
            if (v[j] >= 0.5f) { s = 1.f; v[j] = 0.f; }
            sm[lane][wid * 4 + j] = __float2half(s);
        }
        __syncthreads();
        int nr = wid * 4 + (lane >> 3);
        int cw = (lane & 7) * 4;
        uint2 val = *(const uint2*)&sm[nr][cw];
        *(uint2*)&g_sx[((size_t)((t * kB + b) * kN + n0 + nr)) * kC + c0 + cw] = val;
        __syncthreads();
    }
}

// ---------------------------------------------------------------------------
// FUSED QKV: grid (16 ntiles, 9 = branch*3+mtile, 8 b).
// Loops t=0..3; per t: dual-split fp16 GEMM (K=384) + BN + LIF epilogue.
// LIF membrane state lives in smem (per-thread 32 floats).
//  p=0 (q): spikes -> smem transpose -> g_qb [t,b,n,c]
//  p=1 (k): spikes -> g_kb [t,b,c,n];  p=2 (v): spikes -> g_vb.
// ---------------------------------------------------------------------------
__global__ __launch_bounds__(256, 2) void fused_qkv_kernel(
    const float* __restrict__ qg, const float* __restrict__ qbe, const float* __restrict__ qm, const float* __restrict__ qva,
    const float* __restrict__ kg, const float* __restrict__ kbe, const float* __restrict__ km, const float* __restrict__ kva,
    const float* __restrict__ vg, const float* __restrict__ vbe, const float* __restrict__ vm, const float* __restrict__ vva)
{
    extern __shared__ char dynsm[];
    const uint32_t shb = smem_u32(dynsm);
    float* vsm = (float*)(dynsm + VST_OFF);
    __half* qstage = (__half*)(dynsm + STAGE_BYTES);   // aliases stage 1

    const int tid = threadIdx.x, wid = tid >> 5, lane = tid & 31;
    const int b = blockIdx.z;
    const int yy = blockIdx.y;
    const int p = (yy >= 6) ? 2 : ((yy >= 3) ? 1 : 0);
    const int mtile = yy - p * 3;
    const int m0 = mtile * BM, n0 = blockIdx.x * BN;

    const __half* Abase = g_wqkv + (size_t)(p * 2) * kWelems;
    const int mw = wid >> 1, nw = wid & 1;
    const int gr = lane >> 2, gc = (lane & 3) * 2;
    const int ldrow = lane & 15, ldhalf = lane >> 4;

    // BN params
    const float *G, *Be, *Mn, *Va;
    if (p == 0)      { G = qg; Be = qbe; Mn = qm; Va = qva; }
    else if (p == 1) { G = kg; Be = kbe; Mn = km; Va = kva; }
    else             { G = vg; Be = vbe; Mn = vm; Va = vva; }
    float scv[2][2], mnv[2][2], bev[2][2];
#pragma unroll
    for (int mi = 0; mi < 2; mi++)
#pragma unroll
        for (int half = 0; half < 2; half++) {
            int cc = m0 + mw * 32 + mi * 16 + half * 8 + gr;
            scv[mi][half] = G[cc] / sqrtf(Va[cc] + kEPS);
            mnv[mi][half] = Mn[cc];
            bev[mi][half] = Be[cc];
        }

    // zero LIF state
#pragma unroll
    for (int j = 0; j < 32; j++) vsm[j * 256 + tid] = 0.f;

    auto load_chunk = [&](int t, int ck, int st) {
        const uint32_t sb = shb + st * STAGE_BYTES;
        const int k0 = ck * BK;
#pragma unroll
        for (int it = 0; it < 4; it++) {
            int i = it * 256 + tid;
            int sp = i >> 9, rem = i & 511, r = rem >> 2, kq = rem & 3;
            cp16(sb + ((sp * BM + r) * PITCH + kq * 8) * 2,
                 Abase + (size_t)sp * kWelems + (size_t)(m0 + r) * kC + k0 + kq * 8);
        }
        {
            int r = tid >> 2, kq = tid & 3;
            cp16(sb + (A_ELEMS + r * PITCH + kq * 8) * 2,
                 g_sx + ((size_t)(t * kB + b) * kN + n0 + r) * kC + k0 + kq * 8);
        }
        asm volatile("cp.async.commit_group;");
    };

    for (int t = 0; t < kT; t++) {
        float acch[2][4][4], accl[2][4][4];
#pragma unroll
        for (int i = 0; i < 2; i++)
#pragma unroll
            for (int j = 0; j < 4; j++)
#pragma unroll
                for (int q = 0; q < 4; q++) { acch[i][j][q] = 0.f; accl[i][j][q] = 0.f; }

        load_chunk(t, 0, 0);
        for (int cch = 0; cch < kC / BK; cch++) {
            if (cch + 1 < kC / BK) {
                load_chunk(t, cch + 1, (cch + 1) & 1);
                asm volatile("cp.async.wait_group 1;");
            } else {
                asm volatile("cp.async.wait_group 0;");
            }
            __syncthreads();
            const uint32_t sb = shb + (cch & 1) * STAGE_BYTES;
#pragma unroll
            for (int ks = 0; ks < 2; ks++) {
                const int k0 = ks * 16;
                uint32_t bfr[2][4];
#pragma unroll
                for (int g = 0; g < 2; g++)
                    ldm_x4(bfr[g], sb + (A_ELEMS + (nw * 32 + g * 16 + ldrow) * PITCH + k0 + ldhalf * 8) * 2);
#pragma unroll
                for (int sp = 0; sp < 2; sp++) {
                    uint32_t afr[2][4];
#pragma unroll
                    for (int mi = 0; mi < 2; mi++)
                        ldm_x4(afr[mi], sb + ((sp * BM + mw * 32 + mi * 16 + ldrow) * PITCH + k0 + ldhalf * 8) * 2);
#pragma unroll
                    for (int mi = 0; mi < 2; mi++)
#pragma unroll
                        for (int nj = 0; nj < 4; nj++) {
                            int g = nj >> 1, w = nj & 1;
                            float* acc = (sp == 0) ? acch[mi][nj] : accl[mi][nj];
                            mma16816(acc, afr[mi], bfr[g][w], bfr[g][w + 2]);
                        }
                }
            }
            __syncthreads();
        }

        // ---- BN + LIF epilogue for timestep t ----
#pragma unroll
        for (int mi = 0; mi < 2; mi++)
#pragma unroll
            for (int nj = 0; nj < 4; nj++)
#pragma unroll
                for (int q = 0; q < 4; q++) {
                    const int half = q >> 1;
                    const int j = mi * 16 + nj * 4 + q;
                    float u = (acch[mi][nj][q] + accl[mi][nj][q] * kLoScale - mnv[mi][half]) * scv[mi][half] + bev[mi][half];
                    float vv = vsm[j * 256 + tid];
                    vv += (u - vv) * 0.5f;
                    float s = 0.f;
                    if (vv >= 0.5f) { s = 1.f; vv = 0.f; }
                    vsm[j * 256 + tid] = vv;

                    const int c = m0 + mw * 32 + mi * 16 + half * 8 + gr;
                    const int n = nw * 32 + nj * 8 + gc + (q & 1);
                    if (p == 0) {
                        qstage[n * QPITCH + (c - m0)] = __float2half(s);
                    } else {
                        __half* dst = (p == 1) ? g_kb : g_vb;
                        dst[((size_t)((t * kB + b) * kC + c)) * kN + n0 + n] = __float2half(s);
                    }
                }

        if (p == 0) {
            __syncthreads();
            // coalesced copy-out: 64 rows x 128 halves = 1024 uint4
#pragma unroll
            for (int it = 0; it < 4; it++) {
                int i = it * 256 + tid;
                int n = i >> 4, w = i & 15;
                uint4 val = *(const uint4*)&qstage[n * QPITCH + w * 8];
                *(uint4*)&g_qb[((size_t)((t * kB + b) * kN + n0 + n)) * kC + m0 + w * 8] = val;
            }
            __syncthreads();
        } else {
            __syncthreads();
        }
    }
}

// ---------------------------------------------------------------------------
// kvsum: one warp per (t,b,c) row: sum_n k*v (both binary fp16 -> exact).
// ---------------------------------------------------------------------------
__global__ void kvsum_kernel() {
    const int row = blockIdx.x * 8 + (threadIdx.x >> 5);
    const int lane = threadIdx.x & 31;
    const __half2* kp = (const __half2*)(g_kb + (size_t)row * kN);
    const __half2* vp = (const __half2*)(g_vb + (size_t)row * kN);
    float s = 0.f;
#pragma unroll 4
    for (int i = lane; i < kN / 2; i += 32) {
        __half2 pr = __hmul2(kp[i], vp[i]);
        float2 f = __half22float2(pr);
        s += f.x + f.y;
    }
#pragma unroll
    for (int o = 16; o; o >>= 1) s += __shfl_xor_sync(0xffffffffu, s, o);
    if (lane == 0) g_kvsum[row] = s;
}

// ---------------------------------------------------------------------------
// K4: talking heads + LIF on kv; kv spikes -> fp16.
// ---------------------------------------------------------------------------
__global__ void kv_kernel(const float* __restrict__ th_w) {
    __shared__ float th[64];
    if (threadIdx.x < 64) th[threadIdx.x] = th_w[threadIdx.x];
    __syncthreads();
    int d = threadIdx.x % 48;
    int b = threadIdx.x / 48;
    float v[8];
#pragma unroll
    for (int o = 0; o < 8; o++) v[o] = 0.0f;
#pragma unroll
    for (int t = 0; t < kT; t++) {
        float kvv[8];
#pragma unroll
        for (int h = 0; h < 8; h++)
            kvv[h] = g_kvsum[(t * kB + b) * kC + h * 48 + d];
#pragma unroll
        for (int o = 0; o < 8; o++) {
            float a = 0.0f;
#pragma unroll
            for (int h = 0; h < 8; h++) a += th[o * 8 + h] * kvv[h];
            v[o] += (a - v[o]) * 0.5f;
            float s = 0.f;
            if (v[o] >= 0.5f) { s = 1.f; v[o] = 0.f; }
            g_kvsh[(t * kB + b) * kC + o * 48 + d] = __float2half(s);
        }
    }
}

// ---------------------------------------------------------------------------
// PROJ GEMM: B = q spikes * kvs (kvs folded post-ldmatrix, exact).
// Epilogue: +bias, BN, +identity.
// ---------------------------------------------------------------------------
__global__ __launch_bounds__(256, 2) void gemm_proj_kernel(
    const float* __restrict__ pg, const float* __restrict__ pbe,
    const float* __restrict__ pm, const float* __restrict__ pva,
    const float* __restrict__ bias, const float* __restrict__ xres, float* __restrict__ outp)
{
    extern __shared__ __half sh[];
    const uint32_t shb = smem_u32(sh);

    const int tid = threadIdx.x, wid = tid >> 5, lane = tid & 31;
    const int bz = blockIdx.z, t = bz >> 3, b = bz & 7;
    const int m0 = blockIdx.y * BM, n0 = blockIdx.x * BN;

    const __half* Bimg = g_qb + (size_t)(t * kB + b) * kN * kC;
    const uint32_t* kvsp = (const uint32_t*)(g_kvsh + (t * kB + b) * kC);

    const int mw = wid >> 1, nw = wid & 1;

    float acch[2][4][4], accl[2][4][4];
#pragma unroll
    for (int i = 0; i < 2; i++)
#pragma unroll
        for (int j = 0; j < 4; j++)
#pragma unroll
            for (int q = 0; q < 4; q++) { acch[i][j][q] = 0.f; accl[i][j][q] = 0.f; }

    auto load_chunk = [&](int ck, int st) {
        const uint32_t sb = shb + st * STAGE_BYTES;
        const int k0 = ck * BK;
#pragma unroll
        for (int it = 0; it < 4; it++) {
            int i = it * 256 + tid;
            int sp = i >> 9, rem = i & 511, r = rem >> 2, kq = rem & 3;
            cp16(sb + ((sp * BM + r) * PITCH + kq * 8) * 2,
                 g_wp + (size_t)sp * kWelems + (size_t)(m0 + r) * kC + k0 + kq * 8);
        }
        {
            int r = tid >> 2, kq = tid & 3;
            cp16(sb + (A_ELEMS + r * PITCH + kq * 8) * 2,
                 Bimg + (size_t)(n0 + r) * kC + k0 + kq * 8);
        }
        asm volatile("cp.async.commit_group;");
    };

    load_chunk(0, 0);
    const int ldrow = lane & 15, ldhalf = lane >> 4;

    for (int cch = 0; cch < kC / BK; cch++) {
        if (cch + 1 < kC / BK) {
            load_chunk(cch + 1, (cch + 1) & 1);
            asm volatile("cp.async.wait_group 1;");
        } else {
            asm volatile("cp.async.wait_group 0;");
        }
        __syncthreads();
        const uint32_t sb = shb + (cch & 1) * STAGE_BYTES;
#pragma unroll
        for (int ks = 0; ks < 2; ks++) {
            const int k0 = ks * 16;
            uint32_t bfr[2][4];
#pragma unroll
            for (int g = 0; g < 2; g++)
                ldm_x4(bfr[g], sb + (A_ELEMS + (nw * 32 + g * 16 + ldrow) * PITCH + k0 + ldhalf * 8) * 2);
            {
                uint32_t p0 = kvsp[cch * 16 + ks * 8 + (lane & 3)];
                uint32_t p1 = kvsp[cch * 16 + ks * 8 + 4 + (lane & 3)];
#pragma unroll
                for (int g = 0; g < 2; g++) {
                    bfr[g][0] = hmul2u(bfr[g][0], p0);
                    bfr[g][1] = hmul2u(bfr[g][1], p0);
                    bfr[g][2] = hmul2u(bfr[g][2], p1);
                    bfr[g][3] = hmul2u(bfr[g][3], p1);
                }
            }
#pragma unroll
            for (int sp = 0; sp < 2; sp++) {
                uint32_t afr[2][4];
#pragma unroll
                for (int mi = 0; mi < 2; mi++)
                    ldm_x4(afr[mi], sb + ((sp * BM + mw * 32 + mi * 16 + ldrow) * PITCH + k0 + ldhalf * 8) * 2);
#pragma unroll
                for (int mi = 0; mi < 2; mi++)
#pragma unroll
                    for (int nj = 0; nj < 4; nj++) {
                        int g = nj >> 1, w = nj & 1;
                        float* acc = (sp == 0) ? acch[mi][nj] : accl[mi][nj];
                        mma16816(acc, afr[mi], bfr[g][w], bfr[g][w + 2]);
                    }
            }
        }
        __syncthreads();
    }

    const int gr = lane >> 2, gc = (lane & 3) * 2;
    const size_t imgoff = ((size_t)(t * kB + b) * kC) * kN;

#pragma unroll
    for (int mi = 0; mi < 2; mi++) {
#pragma unroll
        for (int half = 0; half < 2; half++) {
            const int c = m0 + mw * 32 + mi * 16 + gr + half * 8;
            const float sc = pg[c] / sqrtf(pva[c] + kEPS);
            const float mn = pm[c], be = pbe[c];
            const float bi = bias[c];
            size_t rowoff = imgoff + (size_t)c * kN;
            float* dst = outp + rowoff;
#pragma unroll
            for (int nj = 0; nj < 4; nj++) {
                const int n = n0 + nw * 32 + nj * 8 + gc;
                float v0 = acch[mi][nj][half * 2 + 0] + accl[mi][nj][half * 2 + 0] * kLoScale;
                float v1 = acch[mi][nj][half * 2 + 1] + accl[mi][nj][half * 2 + 1] * kLoScale;
                float2 xv = *(const float2*)(xres + rowoff + n);
                float2 o;
                o.x = ((v0 + bi) - mn) * sc + be + xv.x;
                o.y = ((v1 + bi) - mn) * sc + be + xv.y;
                *(float2*)(dst + n) = o;
            }
        }
    }
}

// ---------------------------------------------------------------------------
extern "C" void kernel_launch(void* const* d_in, const int* in_sizes, int n_in,
                              void* d_out, int out_size)
{
    const float* x   = (const float*)d_in[0];
    const float* qw  = (const float*)d_in[1];
    const float* kw  = (const float*)d_in[2];
    const float* vw  = (const float*)d_in[3];
    const float* thw = (const float*)d_in[4];
    const float* pw  = (const float*)d_in[5];
    const float* pb  = (const float*)d_in[6];
    const float* qg  = (const float*)d_in[7];
    const float* qbe = (const float*)d_in[8];
    const float* qm  = (const float*)d_in[9];
    const float* qva = (const float*)d_in[10];
    const float* kg  = (const float*)d_in[11];
    const float* kbe = (const float*)d_in[12];
    const float* km  = (const float*)d_in[13];
    const float* kva = (const float*)d_in[14];
    const float* vg  = (const float*)d_in[15];
    const float* vbe = (const float*)d_in[16];
    const float* vm  = (const float*)d_in[17];
    const float* vva = (const float*)d_in[18];
    const float* pg  = (const float*)d_in[19];
    const float* pbe = (const float*)d_in[20];
    const float* pm  = (const float*)d_in[21];
    const float* pva = (const float*)d_in[22];
    float* out = (float*)d_out;

    cudaFuncSetAttribute(fused_qkv_kernel, cudaFuncAttributeMaxDynamicSharedMemorySize, FSMEM);
    cudaFuncSetAttribute(gemm_proj_kernel, cudaFuncAttributeMaxDynamicSharedMemorySize, SMEM_BYTES);

    split_w_kernel<<<(4 * kWelems + 255) / 256, 256>>>(qw, kw, vw, pw);

    lif_x_kernel<<<dim3(kN / 32, kC / 32, kB), 256>>>(x);

    fused_qkv_kernel<<<dim3(kN / BN, 9, kB), 256, FSMEM>>>(
        qg, qbe, qm, qva, kg, kbe, km, kva, vg, vbe, vm, vva);

    kvsum_kernel<<<kT * kB * kC / 8, 256>>>();

    kv_kernel<<<1, 384>>>(thw);

    gemm_proj_kernel<<<dim3(kN / BN, kC / BM, kT * kB), 256, SMEM_BYTES>>>(
        pg, pbe, pm, pva, pb, x, out);
}

// round 8
// speedup vs baseline: 1.0926x; 1.0926x over previous
#include <cuda_runtime.h>
#include <cuda_fp16.h>
#include <cstdint>
#include <math.h>

constexpr int kT = 4, kB = 8, kC = 384, kN = 1024;
constexpr int kBCN  = kB * kC * kN;
constexpr int kTBCN = kT * kBCN;            // 12,582,912
constexpr float kEPS = 1e-5f;
constexpr int kWelems = kC * kC;            // 147456
constexpr float kLoScale = 1.0f / 4096.0f;

// ---------------- device scratch ----------------
__device__ __half g_wqkv[6 * kWelems];      // [branch*2+split][m][k]  (hi, lo*4096)
__device__ __half g_wp[2 * kWelems];        // [split][m][k]
__device__ __half g_sx[kTBCN];              // input spikes  [t][b][n][c]
__device__ __half g_qb[kTBCN];              // q spikes      [t][b][n][c]
__device__ __half g_kb[kTBCN];              // k spikes      [t][b][c][n]
__device__ __half g_vb[kTBCN];              // v spikes      [t][b][c][n]
__device__ float g_kvsum[kT * kB * kC];
__device__ __half g_kvsh[kT * kB * kC];     // kv spikes (fp16)

// ---------------- helpers ----------------
__device__ __forceinline__ uint32_t smem_u32(const void* p) {
    uint32_t a;
    asm("{ .reg .u64 t; cvta.to.shared.u64 t, %1; cvt.u32.u64 %0, t; }" : "=r"(a) : "l"(p));
    return a;
}
__device__ __forceinline__ void cp16(uint32_t dst, const void* src) {
    asm volatile("cp.async.cg.shared.global [%0], [%1], 16;" :: "r"(dst), "l"(src));
}
__device__ __forceinline__ void ldm_x4(uint32_t* r, uint32_t addr) {
    asm volatile("ldmatrix.sync.aligned.m8n8.x4.shared.b16 {%0,%1,%2,%3}, [%4];"
                 : "=r"(r[0]), "=r"(r[1]), "=r"(r[2]), "=r"(r[3]) : "r"(addr));
}
__device__ __forceinline__ void mma16816(float* c, const uint32_t* a, uint32_t b0, uint32_t b1) {
    asm volatile("mma.sync.aligned.m16n8k16.row.col.f32.f16.f16.f32 "
                 "{%0,%1,%2,%3}, {%4,%5,%6,%7}, {%8,%9}, {%0,%1,%2,%3};"
                 : "+f"(c[0]), "+f"(c[1]), "+f"(c[2]), "+f"(c[3])
                 : "r"(a[0]), "r"(a[1]), "r"(a[2]), "r"(a[3]), "r"(b0), "r"(b1));
}
__device__ __forceinline__ uint32_t hmul2u(uint32_t a, uint32_t b) {
    __half2 r = __hmul2(*(__half2*)&a, *(__half2*)&b);
    return *(uint32_t*)&r;
}

// GEMM tiling: 128(M) x 64(N) x 32(K), 8 warps (4m x 2n), dual-split accumulation.
constexpr int BM = 128, BN = 64, BK = 32;
constexpr int PITCH = 40;                        // half elems per smem row (80B)
constexpr int A_ELEMS = 2 * BM * PITCH;          // 10240 (2 splits)
constexpr int B_ELEMS = BN * PITCH;              // 2560
constexpr int STAGE_ELEMS = A_ELEMS + B_ELEMS;   // 12800
constexpr int STAGE_BYTES = STAGE_ELEMS * 2;     // 25600
// fused kernel smem: 2 stages + LIF-state (256 threads x 32 floats)
constexpr int VST_OFF  = 2 * STAGE_BYTES;        // 51200
constexpr int FSMEM    = VST_OFF + 256 * 32 * 4; // 83968
// spike staging aliases stage 1 (dead during epilogue):
//  q:  64 n-rows x 136 halves (write [n][c])   = 17408 B
//  kv: 128 c-rows x 72 halves (write [c][n])   = 18432 B   (both < 25600)
constexpr int QPITCH = 136;
constexpr int KVP    = 72;

// proj kernel smem: 2 stages only
constexpr int SMEM_BYTES = 2 * STAGE_BYTES;      // 51200

// ---------------------------------------------------------------------------
// K0: split fp32 weights into (hi, lo*4096) fp16 pair.
// ---------------------------------------------------------------------------
__global__ void split_w_kernel(const float* __restrict__ qw, const float* __restrict__ kw,
                               const float* __restrict__ vw, const float* __restrict__ pw) {
    int idx = blockIdx.x * 256 + threadIdx.x;
    if (idx >= 4 * kWelems) return;
    int mat = idx / kWelems;
    int e = idx - mat * kWelems;
    const float* src = (mat == 0) ? qw : (mat == 1) ? kw : (mat == 2) ? vw : pw;
    float w = src[e];
    __half h = __float2half_rn(w);
    __half l = __float2half_rn((w - __half2float(h)) * 4096.0f);
    if (mat < 3) {
        g_wqkv[(mat * 2 + 0) * kWelems + e] = h;
        g_wqkv[(mat * 2 + 1) * kWelems + e] = l;
    } else {
        g_wp[0 * kWelems + e] = h;
        g_wp[1 * kWelems + e] = l;
    }
}

// ---------------------------------------------------------------------------
// K1: LIF on x [t][b][c][n] -> fp16 spikes transposed to [t][b][n][c].
// ---------------------------------------------------------------------------
__global__ void lif_x_kernel(const float* __restrict__ x) {
    __shared__ __half sm[32][36];
    const int lane = threadIdx.x & 31, wid = threadIdx.x >> 5;
    const int n0 = blockIdx.x * 32, c0 = blockIdx.y * 32, b = blockIdx.z;
    float v[4] = {0.f, 0.f, 0.f, 0.f};
    for (int t = 0; t < kT; t++) {
#pragma unroll
        for (int j = 0; j < 4; j++) {
            int c = c0 + wid * 4 + j;
            float xv = x[((size_t)((t * kB + b) * kC + c)) * kN + n0 + lane];
            v[j] += (xv - v[j]) * 0.5f;
            float s = 0.f;
            if (v[j] >= 0.5f) { s = 1.f; v[j] = 0.f; }
            sm[lane][wid * 4 + j] = __float2half(s);
        }
        __syncthreads();
        int nr = wid * 4 + (lane >> 3);
        int cw = (lane & 7) * 4;
        uint2 val = *(const uint2*)&sm[nr][cw];
        *(uint2*)&g_sx[((size_t)((t * kB + b) * kN + n0 + nr)) * kC + c0 + cw] = val;
        __syncthreads();
    }
}

// ---------------------------------------------------------------------------
// FUSED QKV: grid (16 ntiles, 9 = branch*3+mtile, 8 b).
// Loops t=0..3; per t: dual-split fp16 GEMM (K=384) + BN + LIF epilogue.
// LIF membrane state lives in smem. ALL spike outputs staged through smem
// for fully coalesced global stores.
// ---------------------------------------------------------------------------
__global__ __launch_bounds__(256, 2) void fused_qkv_kernel(
    const float* __restrict__ qg, const float* __restrict__ qbe, const float* __restrict__ qm, const float* __restrict__ qva,
    const float* __restrict__ kg, const float* __restrict__ kbe, const float* __restrict__ km, const float* __restrict__ kva,
    const float* __restrict__ vg, const float* __restrict__ vbe, const float* __restrict__ vm, const float* __restrict__ vva)
{
    extern __shared__ char dynsm[];
    const uint32_t shb = smem_u32(dynsm);
    float* vsm = (float*)(dynsm + VST_OFF);
    __half* stg = (__half*)(dynsm + STAGE_BYTES);   // aliases stage 1

    const int tid = threadIdx.x, wid = tid >> 5, lane = tid & 31;
    const int b = blockIdx.z;
    const int yy = blockIdx.y;
    const int p = (yy >= 6) ? 2 : ((yy >= 3) ? 1 : 0);
    const int mtile = yy - p * 3;
    const int m0 = mtile * BM, n0 = blockIdx.x * BN;

    const __half* Abase = g_wqkv + (size_t)(p * 2) * kWelems;
    const int mw = wid >> 1, nw = wid & 1;
    const int gr = lane >> 2, gc = (lane & 3) * 2;
    const int ldrow = lane & 15, ldhalf = lane >> 4;

    // BN params
    const float *G, *Be, *Mn, *Va;
    if (p == 0)      { G = qg; Be = qbe; Mn = qm; Va = qva; }
    else if (p == 1) { G = kg; Be = kbe; Mn = km; Va = kva; }
    else             { G = vg; Be = vbe; Mn = vm; Va = vva; }
    float scv[2][2], mnv[2][2], bev[2][2];
#pragma unroll
    for (int mi = 0; mi < 2; mi++)
#pragma unroll
        for (int half = 0; half < 2; half++) {
            int cc = m0 + mw * 32 + mi * 16 + half * 8 + gr;
            scv[mi][half] = G[cc] / sqrtf(Va[cc] + kEPS);
            mnv[mi][half] = Mn[cc];
            bev[mi][half] = Be[cc];
        }

    // zero LIF state
#pragma unroll
    for (int j = 0; j < 32; j++) vsm[j * 256 + tid] = 0.f;

    auto load_chunk = [&](int t, int ck, int st) {
        const uint32_t sb = shb + st * STAGE_BYTES;
        const int k0 = ck * BK;
#pragma unroll
        for (int it = 0; it < 4; it++) {
            int i = it * 256 + tid;
            int sp = i >> 9, rem = i & 511, r = rem >> 2, kq = rem & 3;
            cp16(sb + ((sp * BM + r) * PITCH + kq * 8) * 2,
                 Abase + (size_t)sp * kWelems + (size_t)(m0 + r) * kC + k0 + kq * 8);
        }
        {
            int r = tid >> 2, kq = tid & 3;
            cp16(sb + (A_ELEMS + r * PITCH + kq * 8) * 2,
                 g_sx + ((size_t)(t * kB + b) * kN + n0 + r) * kC + k0 + kq * 8);
        }
        asm volatile("cp.async.commit_group;");
    };

    for (int t = 0; t < kT; t++) {
        float acch[2][4][4], accl[2][4][4];
#pragma unroll
        for (int i = 0; i < 2; i++)
#pragma unroll
            for (int j = 0; j < 4; j++)
#pragma unroll
                for (int q = 0; q < 4; q++) { acch[i][j][q] = 0.f; accl[i][j][q] = 0.f; }

        load_chunk(t, 0, 0);
        for (int cch = 0; cch < kC / BK; cch++) {
            if (cch + 1 < kC / BK) {
                load_chunk(t, cch + 1, (cch + 1) & 1);
                asm volatile("cp.async.wait_group 1;");
            } else {
                asm volatile("cp.async.wait_group 0;");
            }
            __syncthreads();
            const uint32_t sb = shb + (cch & 1) * STAGE_BYTES;
#pragma unroll
            for (int ks = 0; ks < 2; ks++) {
                const int k0 = ks * 16;
                uint32_t bfr[2][4];
#pragma unroll
                for (int g = 0; g < 2; g++)
                    ldm_x4(bfr[g], sb + (A_ELEMS + (nw * 32 + g * 16 + ldrow) * PITCH + k0 + ldhalf * 8) * 2);
#pragma unroll
                for (int sp = 0; sp < 2; sp++) {
                    uint32_t afr[2][4];
#pragma unroll
                    for (int mi = 0; mi < 2; mi++)
                        ldm_x4(afr[mi], sb + ((sp * BM + mw * 32 + mi * 16 + ldrow) * PITCH + k0 + ldhalf * 8) * 2);
#pragma unroll
                    for (int mi = 0; mi < 2; mi++)
#pragma unroll
                        for (int nj = 0; nj < 4; nj++) {
                            int g = nj >> 1, w = nj & 1;
                            float* acc = (sp == 0) ? acch[mi][nj] : accl[mi][nj];
                            mma16816(acc, afr[mi], bfr[g][w], bfr[g][w + 2]);
                        }
                }
            }
            __syncthreads();
        }

        // ---- BN + LIF epilogue for timestep t (stage spikes into smem) ----
#pragma unroll
        for (int mi = 0; mi < 2; mi++)
#pragma unroll
            for (int nj = 0; nj < 4; nj++)
#pragma unroll
                for (int q = 0; q < 4; q++) {
                    const int half = q >> 1;
                    const int j = mi * 16 + nj * 4 + q;
                    float u = (acch[mi][nj][q] + accl[mi][nj][q] * kLoScale - mnv[mi][half]) * scv[mi][half] + bev[mi][half];
                    float vv = vsm[j * 256 + tid];
                    vv += (u - vv) * 0.5f;
                    float s = 0.f;
                    if (vv >= 0.5f) { s = 1.f; vv = 0.f; }
                    vsm[j * 256 + tid] = vv;

                    const int cl = mw * 32 + mi * 16 + half * 8 + gr;       // 0..127
                    const int n = nw * 32 + nj * 8 + gc + (q & 1);          // 0..63
                    if (p == 0) stg[n * QPITCH + cl] = __float2half(s);
                    else        stg[cl * KVP + n]   = __float2half(s);
                }

        __syncthreads();
        if (p == 0) {
            // coalesced copy-out: 64 n-rows x 128 halves = 1024 uint4
#pragma unroll
            for (int it = 0; it < 4; it++) {
                int i = it * 256 + tid;
                int n = i >> 4, w = i & 15;
                uint4 val = *(const uint4*)&stg[n * QPITCH + w * 8];
                *(uint4*)&g_qb[((size_t)((t * kB + b) * kN + n0 + n)) * kC + m0 + w * 8] = val;
            }
        } else {
            // coalesced copy-out: 128 c-rows x 64 halves = 1024 uint4
            __half* dstb = (p == 1) ? g_kb : g_vb;
#pragma unroll
            for (int it = 0; it < 4; it++) {
                int i = it * 256 + tid;
                int cl = i >> 3, w = i & 7;
                uint4 val = *(const uint4*)&stg[cl * KVP + w * 8];
                *(uint4*)&dstb[((size_t)((t * kB + b) * kC + m0 + cl)) * kN + n0 + w * 8] = val;
            }
        }
        __syncthreads();
    }
}

// ---------------------------------------------------------------------------
// kvsum: one warp per (t,b,c) row: sum_n k*v (both binary fp16 -> exact).
// ---------------------------------------------------------------------------
__global__ void kvsum_kernel() {
    const int row = blockIdx.x * 8 + (threadIdx.x >> 5);
    const int lane = threadIdx.x & 31;
    const uint2* kp = (const uint2*)(g_kb + (size_t)row * kN);
    const uint2* vp = (const uint2*)(g_vb + (size_t)row * kN);
    float s = 0.f;
#pragma unroll
    for (int i = lane; i < kN / 4; i += 32) {
        uint2 kv4 = kp[i], vv4 = vp[i];
        __half2 p0 = __hmul2(*(__half2*)&kv4.x, *(__half2*)&vv4.x);
        __half2 p1 = __hmul2(*(__half2*)&kv4.y, *(__half2*)&vv4.y);
        float2 f0 = __half22float2(p0), f1 = __half22float2(p1);
        s += (f0.x + f0.y) + (f1.x + f1.y);
    }
#pragma unroll
    for (int o = 16; o; o >>= 1) s += __shfl_xor_sync(0xffffffffu, s, o);
    if (lane == 0) g_kvsum[row] = s;
}

// ---------------------------------------------------------------------------
// K4: talking heads + LIF on kv; kv spikes -> fp16.
// ---------------------------------------------------------------------------
__global__ void kv_kernel(const float* __restrict__ th_w) {
    __shared__ float th[64];
    if (threadIdx.x < 64) th[threadIdx.x] = th_w[threadIdx.x];
    __syncthreads();
    int d = threadIdx.x % 48;
    int b = threadIdx.x / 48;
    float v[8];
#pragma unroll
    for (int o = 0; o < 8; o++) v[o] = 0.0f;
#pragma unroll
    for (int t = 0; t < kT; t++) {
        float kvv[8];
#pragma unroll
        for (int h = 0; h < 8; h++)
            kvv[h] = g_kvsum[(t * kB + b) * kC + h * 48 + d];
#pragma unroll
        for (int o = 0; o < 8; o++) {
            float a = 0.0f;
#pragma unroll
            for (int h = 0; h < 8; h++) a += th[o * 8 + h] * kvv[h];
            v[o] += (a - v[o]) * 0.5f;
            float s = 0.f;
            if (v[o] >= 0.5f) { s = 1.f; v[o] = 0.f; }
            g_kvsh[(t * kB + b) * kC + o * 48 + d] = __float2half(s);
        }
    }
}

// ---------------------------------------------------------------------------
// PROJ GEMM: B = q spikes * kvs (kvs folded post-ldmatrix, exact).
// Epilogue: +bias, BN, +identity.
// ---------------------------------------------------------------------------
__global__ __launch_bounds__(256, 2) void gemm_proj_kernel(
    const float* __restrict__ pg, const float* __restrict__ pbe,
    const float* __restrict__ pm, const float* __restrict__ pva,
    const float* __restrict__ bias, const float* __restrict__ xres, float* __restrict__ outp)
{
    extern __shared__ __half sh[];
    const uint32_t shb = smem_u32(sh);

    const int tid = threadIdx.x, wid = tid >> 5, lane = tid & 31;
    const int bz = blockIdx.z, t = bz >> 3, b = bz & 7;
    const int m0 = blockIdx.y * BM, n0 = blockIdx.x * BN;

    const __half* Bimg = g_qb + (size_t)(t * kB + b) * kN * kC;
    const uint32_t* kvsp = (const uint32_t*)(g_kvsh + (t * kB + b) * kC);

    const int mw = wid >> 1, nw = wid & 1;

    float acch[2][4][4], accl[2][4][4];
#pragma unroll
    for (int i = 0; i < 2; i++)
#pragma unroll
        for (int j = 0; j < 4; j++)
#pragma unroll
            for (int q = 0; q < 4; q++) { acch[i][j][q] = 0.f; accl[i][j][q] = 0.f; }

    auto load_chunk = [&](int ck, int st) {
        const uint32_t sb = shb + st * STAGE_BYTES;
        const int k0 = ck * BK;
#pragma unroll
        for (int it = 0; it < 4; it++) {
            int i = it * 256 + tid;
            int sp = i >> 9, rem = i & 511, r = rem >> 2, kq = rem & 3;
            cp16(sb + ((sp * BM + r) * PITCH + kq * 8) * 2,
                 g_wp + (size_t)sp * kWelems + (size_t)(m0 + r) * kC + k0 + kq * 8);
        }
        {
            int r = tid >> 2, kq = tid & 3;
            cp16(sb + (A_ELEMS + r * PITCH + kq * 8) * 2,
                 Bimg + (size_t)(n0 + r) * kC + k0 + kq * 8);
        }
        asm volatile("cp.async.commit_group;");
    };

    load_chunk(0, 0);
    const int ldrow = lane & 15, ldhalf = lane >> 4;

    for (int cch = 0; cch < kC / BK; cch++) {
        if (cch + 1 < kC / BK) {
            load_chunk(cch + 1, (cch + 1) & 1);
            asm volatile("cp.async.wait_group 1;");
        } else {
            asm volatile("cp.async.wait_group 0;");
        }
        __syncthreads();
        const uint32_t sb = shb + (cch & 1) * STAGE_BYTES;
#pragma unroll
        for (int ks = 0; ks < 2; ks++) {
            const int k0 = ks * 16;
            uint32_t bfr[2][4];
#pragma unroll
            for (int g = 0; g < 2; g++)
                ldm_x4(bfr[g], sb + (A_ELEMS + (nw * 32 + g * 16 + ldrow) * PITCH + k0 + ldhalf * 8) * 2);
            {
                uint32_t p0 = kvsp[cch * 16 + ks * 8 + (lane & 3)];
                uint32_t p1 = kvsp[cch * 16 + ks * 8 + 4 + (lane & 3)];
#pragma unroll
                for (int g = 0; g < 2; g++) {
                    bfr[g][0] = hmul2u(bfr[g][0], p0);
                    bfr[g][1] = hmul2u(bfr[g][1], p0);
                    bfr[g][2] = hmul2u(bfr[g][2], p1);
                    bfr[g][3] = hmul2u(bfr[g][3], p1);
                }
            }
#pragma unroll
            for (int sp = 0; sp < 2; sp++) {
                uint32_t afr[2][4];
#pragma unroll
                for (int mi = 0; mi < 2; mi++)
                    ldm_x4(afr[mi], sb + ((sp * BM + mw * 32 + mi * 16 + ldrow) * PITCH + k0 + ldhalf * 8) * 2);
#pragma unroll
                for (int mi = 0; mi < 2; mi++)
#pragma unroll
                    for (int nj = 0; nj < 4; nj++) {
                        int g = nj >> 1, w = nj & 1;
                        float* acc = (sp == 0) ? acch[mi][nj] : accl[mi][nj];
                        mma16816(acc, afr[mi], bfr[g][w], bfr[g][w + 2]);
                    }
            }
        }
        __syncthreads();
    }

    const int gr = lane >> 2, gc = (lane & 3) * 2;
    const size_t imgoff = ((size_t)(t * kB + b) * kC) * kN;

#pragma unroll
    for (int mi = 0; mi < 2; mi++) {
#pragma unroll
        for (int half = 0; half < 2; half++) {
            const int c = m0 + mw * 32 + mi * 16 + gr + half * 8;
            const float sc = pg[c] / sqrtf(pva[c] + kEPS);
            const float mn = pm[c], be = pbe[c];
            const float bi = bias[c];
            size_t rowoff = imgoff + (size_t)c * kN;
            float* dst = outp + rowoff;
#pragma unroll
            for (int nj = 0; nj < 4; nj++) {
                const int n = n0 + nw * 32 + nj * 8 + gc;
                float v0 = acch[mi][nj][half * 2 + 0] + accl[mi][nj][half * 2 + 0] * kLoScale;
                float v1 = acch[mi][nj][half * 2 + 1] + accl[mi][nj][half * 2 + 1] * kLoScale;
                float2 xv = *(const float2*)(xres + rowoff + n);
                float2 o;
                o.x = ((v0 + bi) - mn) * sc + be + xv.x;
                o.y = ((v1 + bi) - mn) * sc + be + xv.y;
                *(float2*)(dst + n) = o;
            }
        }
    }
}

// ---------------------------------------------------------------------------
extern "C" void kernel_launch(void* const* d_in, const int* in_sizes, int n_in,
                              void* d_out, int out_size)
{
    const float* x   = (const float*)d_in[0];
    const float* qw  = (const float*)d_in[1];
    const float* kw  = (const float*)d_in[2];
    const float* vw  = (const float*)d_in[3];
    const float* thw = (const float*)d_in[4];
    const float* pw  = (const float*)d_in[5];
    const float* pb  = (const float*)d_in[6];
    const float* qg  = (const float*)d_in[7];
    const float* qbe = (const float*)d_in[8];
    const float* qm  = (const float*)d_in[9];
    const float* qva = (const float*)d_in[10];
    const float* kg  = (const float*)d_in[11];
    const float* kbe = (const float*)d_in[12];
    const float* km  = (const float*)d_in[13];
    const float* kva = (const float*)d_in[14];
    const float* vg  = (const float*)d_in[15];
    const float* vbe = (const float*)d_in[16];
    const float* vm  = (const float*)d_in[17];
    const float* vva = (const float*)d_in[18];
    const float* pg  = (const float*)d_in[19];
    const float* pbe = (const float*)d_in[20];
    const float* pm  = (const float*)d_in[21];
    const float* pva = (const float*)d_in[22];
    float* out = (float*)d_out;

    cudaFuncSetAttribute(fused_qkv_kernel, cudaFuncAttributeMaxDynamicSharedMemorySize, FSMEM);
    cudaFuncSetAttribute(gemm_proj_kernel, cudaFuncAttributeMaxDynamicSharedMemorySize, SMEM_BYTES);

    split_w_kernel<<<(4 * kWelems + 255) / 256, 256>>>(qw, kw, vw, pw);

    lif_x_kernel<<<dim3(kN / 32, kC / 32, kB), 256>>>(x);

    fused_qkv_kernel<<<dim3(kN / BN, 9, kB), 256, FSMEM>>>(
        qg, qbe, qm, qva, kg, kbe, km, kva, vg, vbe, vm, vva);

    kvsum_kernel<<<kT * kB * kC / 8, 256>>>();

    kv_kernel<<<1, 384>>>(thw);

    gemm_proj_kernel<<<dim3(kN / BN, kC / BM, kT * kB), 256, SMEM_BYTES>>>(
        pg, pbe, pm, pva, pb, x, out);
}

// round 9
// speedup vs baseline: 1.2133x; 1.1104x over previous
#include <cuda_runtime.h>
#include <cuda_fp16.h>
#include <cstdint>
#include <math.h>

constexpr int kT = 4, kB = 8, kC = 384, kN = 1024;
constexpr int kBCN  = kB * kC * kN;
constexpr int kTBCN = kT * kBCN;            // 12,582,912
constexpr float kEPS = 1e-5f;
constexpr int kWelems = kC * kC;            // 147456
constexpr float kLoScale = 1.0f / 4096.0f;

// ---------------- device scratch ----------------
__device__ __half g_wqkv[6 * kWelems];      // [branch*2+split][m][k]  (hi, lo*4096)
__device__ __half g_wp[2 * kWelems];        // [split][m][k] (proj uses hi only)
__device__ __half g_sx[kTBCN];              // input spikes  [t][b][n][c]
__device__ __half g_qb[kTBCN];              // q spikes      [t][b][n][c]
__device__ __half g_kb[kTBCN];              // k spikes      [t][b][c][n]
__device__ __half g_vb[kTBCN];              // v spikes      [t][b][c][n]
__device__ float g_kvsum[kT * kB * kC];
__device__ __half g_kvsh[kT * kB * kC];     // kv spikes (fp16)

// ---------------- helpers ----------------
__device__ __forceinline__ uint32_t smem_u32(const void* p) {
    uint32_t a;
    asm("{ .reg .u64 t; cvta.to.shared.u64 t, %1; cvt.u32.u64 %0, t; }" : "=r"(a) : "l"(p));
    return a;
}
__device__ __forceinline__ void cp16(uint32_t dst, const void* src) {
    asm volatile("cp.async.cg.shared.global [%0], [%1], 16;" :: "r"(dst), "l"(src));
}
__device__ __forceinline__ void ldm_x4(uint32_t* r, uint32_t addr) {
    asm volatile("ldmatrix.sync.aligned.m8n8.x4.shared.b16 {%0,%1,%2,%3}, [%4];"
                 : "=r"(r[0]), "=r"(r[1]), "=r"(r[2]), "=r"(r[3]) : "r"(addr));
}
__device__ __forceinline__ void mma16816(float* c, const uint32_t* a, uint32_t b0, uint32_t b1) {
    asm volatile("mma.sync.aligned.m16n8k16.row.col.f32.f16.f16.f32 "
                 "{%0,%1,%2,%3}, {%4,%5,%6,%7}, {%8,%9}, {%0,%1,%2,%3};"
                 : "+f"(c[0]), "+f"(c[1]), "+f"(c[2]), "+f"(c[3])
                 : "r"(a[0]), "r"(a[1]), "r"(a[2]), "r"(a[3]), "r"(b0), "r"(b1));
}
__device__ __forceinline__ uint32_t hmul2u(uint32_t a, uint32_t b) {
    __half2 r = __hmul2(*(__half2*)&a, *(__half2*)&b);
    return *(uint32_t*)&r;
}

// GEMM tiling: 128(M) x 64(N) x 32(K), 8 warps (4m x 2n).
constexpr int BM = 128, BN = 64, BK = 32;
constexpr int PITCH = 40;                        // half elems per smem row (80B)
constexpr int A_ELEMS = 2 * BM * PITCH;          // 10240 (2 splits, fused qkv)
constexpr int B_ELEMS = BN * PITCH;              // 2560
constexpr int STAGE_ELEMS = A_ELEMS + B_ELEMS;   // 12800
constexpr int STAGE_BYTES = STAGE_ELEMS * 2;     // 25600
// fused kernel smem: 2 stages + LIF-state (256 threads x 32 floats)
constexpr int VST_OFF  = 2 * STAGE_BYTES;        // 51200
constexpr int FSMEM    = VST_OFF + 256 * 32 * 4; // 83968
// spike staging aliases stage 1 (dead during epilogue)
constexpr int QPITCH = 136;
constexpr int KVP    = 72;

// proj kernel: single split
constexpr int PJA_ELEMS = BM * PITCH;                 // 5120
constexpr int PJSTAGE_ELEMS = PJA_ELEMS + B_ELEMS;    // 7680
constexpr int PJSTAGE_BYTES = PJSTAGE_ELEMS * 2;      // 15360
constexpr int PJSMEM = 2 * PJSTAGE_BYTES;             // 30720

// ---------------------------------------------------------------------------
// K0: split fp32 weights into (hi, lo*4096) fp16 pair.
// ---------------------------------------------------------------------------
__global__ void split_w_kernel(const float* __restrict__ qw, const float* __restrict__ kw,
                               const float* __restrict__ vw, const float* __restrict__ pw) {
    int idx = blockIdx.x * 256 + threadIdx.x;
    if (idx >= 4 * kWelems) return;
    int mat = idx / kWelems;
    int e = idx - mat * kWelems;
    const float* src = (mat == 0) ? qw : (mat == 1) ? kw : (mat == 2) ? vw : pw;
    float w = src[e];
    __half h = __float2half_rn(w);
    __half l = __float2half_rn((w - __half2float(h)) * 4096.0f);
    if (mat < 3) {
        g_wqkv[(mat * 2 + 0) * kWelems + e] = h;
        g_wqkv[(mat * 2 + 1) * kWelems + e] = l;
    } else {
        g_wp[0 * kWelems + e] = h;
        g_wp[1 * kWelems + e] = l;
    }
}

// ---------------------------------------------------------------------------
// K1: LIF on x [t][b][c][n] -> fp16 spikes transposed to [t][b][n][c].
// ---------------------------------------------------------------------------
__global__ void lif_x_kernel(const float* __restrict__ x) {
    __shared__ __half sm[32][36];
    const int lane = threadIdx.x & 31, wid = threadIdx.x >> 5;
    const int n0 = blockIdx.x * 32, c0 = blockIdx.y * 32, b = blockIdx.z;
    float v[4] = {0.f, 0.f, 0.f, 0.f};
    for (int t = 0; t < kT; t++) {
#pragma unroll
        for (int j = 0; j < 4; j++) {
            int c = c0 + wid * 4 + j;
            float xv = x[((size_t)((t * kB + b) * kC + c)) * kN + n0 + lane];
            v[j] += (xv - v[j]) * 0.5f;
            float s = 0.f;
            if (v[j] >= 0.5f) { s = 1.f; v[j] = 0.f; }
            sm[lane][wid * 4 + j] = __float2half(s);
        }
        __syncthreads();
        int nr = wid * 4 + (lane >> 3);
        int cw = (lane & 7) * 4;
        uint2 val = *(const uint2*)&sm[nr][cw];
        *(uint2*)&g_sx[((size_t)((t * kB + b) * kN + n0 + nr)) * kC + c0 + cw] = val;
        __syncthreads();
    }
}

// ---------------------------------------------------------------------------
// FUSED QKV: grid (16 ntiles, 9 = branch*3+mtile, 8 b).
// Loops t; per t: dual-split fp16 GEMM + BN + LIF epilogue; spikes staged in
// smem for coalesced stores. Prefetches (t+1, chunk0) during t's tail.
// ---------------------------------------------------------------------------
__global__ __launch_bounds__(256, 2) void fused_qkv_kernel(
    const float* __restrict__ qg, const float* __restrict__ qbe, const float* __restrict__ qm, const float* __restrict__ qva,
    const float* __restrict__ kg, const float* __restrict__ kbe, const float* __restrict__ km, const float* __restrict__ kva,
    const float* __restrict__ vg, const float* __restrict__ vbe, const float* __restrict__ vm, const float* __restrict__ vva)
{
    extern __shared__ char dynsm[];
    const uint32_t shb = smem_u32(dynsm);
    float* vsm = (float*)(dynsm + VST_OFF);
    __half* stg = (__half*)(dynsm + STAGE_BYTES);   // aliases stage 1

    const int tid = threadIdx.x, wid = tid >> 5, lane = tid & 31;
    const int b = blockIdx.z;
    const int yy = blockIdx.y;
    const int p = (yy >= 6) ? 2 : ((yy >= 3) ? 1 : 0);
    const int mtile = yy - p * 3;
    const int m0 = mtile * BM, n0 = blockIdx.x * BN;

    const __half* Abase = g_wqkv + (size_t)(p * 2) * kWelems;
    const int mw = wid >> 1, nw = wid & 1;
    const int gr = lane >> 2, gc = (lane & 3) * 2;
    const int ldrow = lane & 15, ldhalf = lane >> 4;

    const float *G, *Be, *Mn, *Va;
    if (p == 0)      { G = qg; Be = qbe; Mn = qm; Va = qva; }
    else if (p == 1) { G = kg; Be = kbe; Mn = km; Va = kva; }
    else             { G = vg; Be = vbe; Mn = vm; Va = vva; }
    float scv[2][2], mnv[2][2], bev[2][2];
#pragma unroll
    for (int mi = 0; mi < 2; mi++)
#pragma unroll
        for (int half = 0; half < 2; half++) {
            int cc = m0 + mw * 32 + mi * 16 + half * 8 + gr;
            scv[mi][half] = G[cc] / sqrtf(Va[cc] + kEPS);
            mnv[mi][half] = Mn[cc];
            bev[mi][half] = Be[cc];
        }

#pragma unroll
    for (int j = 0; j < 32; j++) vsm[j * 256 + tid] = 0.f;

    auto load_chunk = [&](int t, int ck, int st) {
        const uint32_t sb = shb + st * STAGE_BYTES;
        const int k0 = ck * BK;
#pragma unroll
        for (int it = 0; it < 4; it++) {
            int i = it * 256 + tid;
            int sp = i >> 9, rem = i & 511, r = rem >> 2, kq = rem & 3;
            cp16(sb + ((sp * BM + r) * PITCH + kq * 8) * 2,
                 Abase + (size_t)sp * kWelems + (size_t)(m0 + r) * kC + k0 + kq * 8);
        }
        {
            int r = tid >> 2, kq = tid & 3;
            cp16(sb + (A_ELEMS + r * PITCH + kq * 8) * 2,
                 g_sx + ((size_t)(t * kB + b) * kN + n0 + r) * kC + k0 + kq * 8);
        }
        asm volatile("cp.async.commit_group;");
    };

    load_chunk(0, 0, 0);
    for (int t = 0; t < kT; t++) {
        float acch[2][4][4], accl[2][4][4];
#pragma unroll
        for (int i = 0; i < 2; i++)
#pragma unroll
            for (int j = 0; j < 4; j++)
#pragma unroll
                for (int q = 0; q < 4; q++) { acch[i][j][q] = 0.f; accl[i][j][q] = 0.f; }

        for (int cch = 0; cch < kC / BK; cch++) {
            if (cch + 1 < kC / BK) {
                load_chunk(t, cch + 1, (cch + 1) & 1);
                asm volatile("cp.async.wait_group 1;");
            } else {
                // prefetch next t's chunk0 into stage 0 (stage 1 holds current last chunk)
                if (t + 1 < kT) {
                    load_chunk(t + 1, 0, 0);
                    asm volatile("cp.async.wait_group 1;");
                } else {
                    asm volatile("cp.async.wait_group 0;");
                }
            }
            __syncthreads();
            const uint32_t sb = shb + (cch & 1) * STAGE_BYTES;
#pragma unroll
            for (int ks = 0; ks < 2; ks++) {
                const int k0 = ks * 16;
                uint32_t bfr[2][4];
#pragma unroll
                for (int g = 0; g < 2; g++)
                    ldm_x4(bfr[g], sb + (A_ELEMS + (nw * 32 + g * 16 + ldrow) * PITCH + k0 + ldhalf * 8) * 2);
#pragma unroll
                for (int sp = 0; sp < 2; sp++) {
                    uint32_t afr[2][4];
#pragma unroll
                    for (int mi = 0; mi < 2; mi++)
                        ldm_x4(afr[mi], sb + ((sp * BM + mw * 32 + mi * 16 + ldrow) * PITCH + k0 + ldhalf * 8) * 2);
#pragma unroll
                    for (int mi = 0; mi < 2; mi++)
#pragma unroll
                        for (int nj = 0; nj < 4; nj++) {
                            int g = nj >> 1, w = nj & 1;
                            float* acc = (sp == 0) ? acch[mi][nj] : accl[mi][nj];
                            mma16816(acc, afr[mi], bfr[g][w], bfr[g][w + 2]);
                        }
                }
            }
            __syncthreads();
        }

        // ---- BN + LIF epilogue for timestep t ----
#pragma unroll
        for (int mi = 0; mi < 2; mi++)
#pragma unroll
            for (int nj = 0; nj < 4; nj++)
#pragma unroll
                for (int q = 0; q < 4; q++) {
                    const int half = q >> 1;
                    const int j = mi * 16 + nj * 4 + q;
                    float u = (acch[mi][nj][q] + accl[mi][nj][q] * kLoScale - mnv[mi][half]) * scv[mi][half] + bev[mi][half];
                    float vv = vsm[j * 256 + tid];
                    vv += (u - vv) * 0.5f;
                    float s = 0.f;
                    if (vv >= 0.5f) { s = 1.f; vv = 0.f; }
                    vsm[j * 256 + tid] = vv;

                    const int cl = mw * 32 + mi * 16 + half * 8 + gr;
                    const int n = nw * 32 + nj * 8 + gc + (q & 1);
                    if (p == 0) stg[n * QPITCH + cl] = __float2half(s);
                    else        stg[cl * KVP + n]   = __float2half(s);
                }

        __syncthreads();
        if (p == 0) {
#pragma unroll
            for (int it = 0; it < 4; it++) {
                int i = it * 256 + tid;
                int n = i >> 4, w = i & 15;
                uint4 val = *(const uint4*)&stg[n * QPITCH + w * 8];
                *(uint4*)&g_qb[((size_t)((t * kB + b) * kN + n0 + n)) * kC + m0 + w * 8] = val;
            }
        } else {
            __half* dstb = (p == 1) ? g_kb : g_vb;
#pragma unroll
            for (int it = 0; it < 4; it++) {
                int i = it * 256 + tid;
                int cl = i >> 3, w = i & 7;
                uint4 val = *(const uint4*)&stg[cl * KVP + w * 8];
                *(uint4*)&dstb[((size_t)((t * kB + b) * kC + m0 + cl)) * kN + n0 + w * 8] = val;
            }
        }
        __syncthreads();
    }
}

// ---------------------------------------------------------------------------
// kvsum: one warp per (t,b,c) row: sum_n k*v (binary fp16 -> exact).
// ---------------------------------------------------------------------------
__global__ void kvsum_kernel() {
    const int row = blockIdx.x * 8 + (threadIdx.x >> 5);
    const int lane = threadIdx.x & 31;
    const uint2* kp = (const uint2*)(g_kb + (size_t)row * kN);
    const uint2* vp = (const uint2*)(g_vb + (size_t)row * kN);
    float s = 0.f;
#pragma unroll
    for (int i = lane; i < kN / 4; i += 32) {
        uint2 kv4 = kp[i], vv4 = vp[i];
        __half2 p0 = __hmul2(*(__half2*)&kv4.x, *(__half2*)&vv4.x);
        __half2 p1 = __hmul2(*(__half2*)&kv4.y, *(__half2*)&vv4.y);
        float2 f0 = __half22float2(p0), f1 = __half22float2(p1);
        s += (f0.x + f0.y) + (f1.x + f1.y);
    }
#pragma unroll
    for (int o = 16; o; o >>= 1) s += __shfl_xor_sync(0xffffffffu, s, o);
    if (lane == 0) g_kvsum[row] = s;
}

// ---------------------------------------------------------------------------
// K4: talking heads + LIF on kv; kv spikes -> fp16.
// ---------------------------------------------------------------------------
__global__ void kv_kernel(const float* __restrict__ th_w) {
    __shared__ float th[64];
    if (threadIdx.x < 64) th[threadIdx.x] = th_w[threadIdx.x];
    __syncthreads();
    int d = threadIdx.x % 48;
    int b = threadIdx.x / 48;
    float v[8];
#pragma unroll
    for (int o = 0; o < 8; o++) v[o] = 0.0f;
#pragma unroll
    for (int t = 0; t < kT; t++) {
        float kvv[8];
#pragma unroll
        for (int h = 0; h < 8; h++)
            kvv[h] = g_kvsum[(t * kB + b) * kC + h * 48 + d];
#pragma unroll
        for (int o = 0; o < 8; o++) {
            float a = 0.0f;
#pragma unroll
            for (int h = 0; h < 8; h++) a += th[o * 8 + h] * kvv[h];
            v[o] += (a - v[o]) * 0.5f;
            float s = 0.f;
            if (v[o] >= 0.5f) { s = 1.f; v[o] = 0.f; }
            g_kvsh[(t * kB + b) * kC + o * 48 + d] = __float2half(s);
        }
    }
}

// ---------------------------------------------------------------------------
// PROJ GEMM: hi-split only (no spike threshold downstream; error ~1e-4).
// B = q spikes * kvs (folded post-ldmatrix, exact).
// ---------------------------------------------------------------------------
__global__ __launch_bounds__(256, 3) void gemm_proj_kernel(
    const float* __restrict__ pg, const float* __restrict__ pbe,
    const float* __restrict__ pm, const float* __restrict__ pva,
    const float* __restrict__ bias, const float* __restrict__ xres, float* __restrict__ outp)
{
    extern __shared__ __half sh[];
    const uint32_t shb = smem_u32(sh);

    const int tid = threadIdx.x, wid = tid >> 5, lane = tid & 31;
    const int bz = blockIdx.z, t = bz >> 3, b = bz & 7;
    const int m0 = blockIdx.y * BM, n0 = blockIdx.x * BN;

    const __half* Bimg = g_qb + (size_t)(t * kB + b) * kN * kC;
    const uint32_t* kvsp = (const uint32_t*)(g_kvsh + (t * kB + b) * kC);

    const int mw = wid >> 1, nw = wid & 1;

    float acch[2][4][4];
#pragma unroll
    for (int i = 0; i < 2; i++)
#pragma unroll
        for (int j = 0; j < 4; j++)
#pragma unroll
            for (int q = 0; q < 4; q++) acch[i][j][q] = 0.f;

    auto load_chunk = [&](int ck, int st) {
        const uint32_t sb = shb + st * PJSTAGE_BYTES;
        const int k0 = ck * BK;
#pragma unroll
        for (int it = 0; it < 2; it++) {
            int i = it * 256 + tid;
            int r = i >> 2, kq = i & 3;
            cp16(sb + (r * PITCH + kq * 8) * 2,
                 g_wp + (size_t)(m0 + r) * kC + k0 + kq * 8);
        }
        {
            int r = tid >> 2, kq = tid & 3;
            cp16(sb + (PJA_ELEMS + r * PITCH + kq * 8) * 2,
                 Bimg + (size_t)(n0 + r) * kC + k0 + kq * 8);
        }
        asm volatile("cp.async.commit_group;");
    };

    load_chunk(0, 0);
    const int ldrow = lane & 15, ldhalf = lane >> 4;

    for (int cch = 0; cch < kC / BK; cch++) {
        if (cch + 1 < kC / BK) {
            load_chunk(cch + 1, (cch + 1) & 1);
            asm volatile("cp.async.wait_group 1;");
        } else {
            asm volatile("cp.async.wait_group 0;");
        }
        __syncthreads();
        const uint32_t sb = shb + (cch & 1) * PJSTAGE_BYTES;
#pragma unroll
        for (int ks = 0; ks < 2; ks++) {
            const int k0 = ks * 16;
            uint32_t bfr[2][4];
#pragma unroll
            for (int g = 0; g < 2; g++)
                ldm_x4(bfr[g], sb + (PJA_ELEMS + (nw * 32 + g * 16 + ldrow) * PITCH + k0 + ldhalf * 8) * 2);
            {
                uint32_t p0 = kvsp[cch * 16 + ks * 8 + (lane & 3)];
                uint32_t p1 = kvsp[cch * 16 + ks * 8 + 4 + (lane & 3)];
#pragma unroll
                for (int g = 0; g < 2; g++) {
                    bfr[g][0] = hmul2u(bfr[g][0], p0);
                    bfr[g][1] = hmul2u(bfr[g][1], p0);
                    bfr[g][2] = hmul2u(bfr[g][2], p1);
                    bfr[g][3] = hmul2u(bfr[g][3], p1);
                }
            }
            uint32_t afr[2][4];
#pragma unroll
            for (int mi = 0; mi < 2; mi++)
                ldm_x4(afr[mi], sb + ((mw * 32 + mi * 16 + ldrow) * PITCH + k0 + ldhalf * 8) * 2);
#pragma unroll
            for (int mi = 0; mi < 2; mi++)
#pragma unroll
                for (int nj = 0; nj < 4; nj++) {
                    int g = nj >> 1, w = nj & 1;
                    mma16816(acch[mi][nj], afr[mi], bfr[g][w], bfr[g][w + 2]);
                }
        }
        __syncthreads();
    }

    const int gr = lane >> 2, gc = (lane & 3) * 2;
    const size_t imgoff = ((size_t)(t * kB + b) * kC) * kN;

#pragma unroll
    for (int mi = 0; mi < 2; mi++) {
#pragma unroll
        for (int half = 0; half < 2; half++) {
            const int c = m0 + mw * 32 + mi * 16 + gr + half * 8;
            const float sc = pg[c] / sqrtf(pva[c] + kEPS);
            const float mn = pm[c], be = pbe[c];
            const float bi = bias[c];
            size_t rowoff = imgoff + (size_t)c * kN;
            float* dst = outp + rowoff;
#pragma unroll
            for (int nj = 0; nj < 4; nj++) {
                const int n = n0 + nw * 32 + nj * 8 + gc;
                float v0 = acch[mi][nj][half * 2 + 0];
                float v1 = acch[mi][nj][half * 2 + 1];
                float2 xv = *(const float2*)(xres + rowoff + n);
                float2 o;
                o.x = ((v0 + bi) - mn) * sc + be + xv.x;
                o.y = ((v1 + bi) - mn) * sc + be + xv.y;
                *(float2*)(dst + n) = o;
            }
        }
    }
}

// ---------------------------------------------------------------------------
extern "C" void kernel_launch(void* const* d_in, const int* in_sizes, int n_in,
                              void* d_out, int out_size)
{
    const float* x   = (const float*)d_in[0];
    const float* qw  = (const float*)d_in[1];
    const float* kw  = (const float*)d_in[2];
    const float* vw  = (const float*)d_in[3];
    const float* thw = (const float*)d_in[4];
    const float* pw  = (const float*)d_in[5];
    const float* pb  = (const float*)d_in[6];
    const float* qg  = (const float*)d_in[7];
    const float* qbe = (const float*)d_in[8];
    const float* qm  = (const float*)d_in[9];
    const float* qva = (const float*)d_in[10];
    const float* kg  = (const float*)d_in[11];
    const float* kbe = (const float*)d_in[12];
    const float* km  = (const float*)d_in[13];
    const float* kva = (const float*)d_in[14];
    const float* vg  = (const float*)d_in[15];
    const float* vbe = (const float*)d_in[16];
    const float* vm  = (const float*)d_in[17];
    const float* vva = (const float*)d_in[18];
    const float* pg  = (const float*)d_in[19];
    const float* pbe = (const float*)d_in[20];
    const float* pm  = (const float*)d_in[21];
    const float* pva = (const float*)d_in[22];
    float* out = (float*)d_out;

    cudaFuncSetAttribute(fused_qkv_kernel, cudaFuncAttributeMaxDynamicSharedMemorySize, FSMEM);
    cudaFuncSetAttribute(gemm_proj_kernel, cudaFuncAttributeMaxDynamicSharedMemorySize, PJSMEM);

    split_w_kernel<<<(4 * kWelems + 255) / 256, 256>>>(qw, kw, vw, pw);

    lif_x_kernel<<<dim3(kN / 32, kC / 32, kB), 256>>>(x);

    fused_qkv_kernel<<<dim3(kN / BN, 9, kB), 256, FSMEM>>>(
        qg, qbe, qm, qva, kg, kbe, km, kva, vg, vbe, vm, vva);

    kvsum_kernel<<<kT * kB * kC / 8, 256>>>();

    kv_kernel<<<1, 384>>>(thw);

    gemm_proj_kernel<<<dim3(kN / BN, kC / BM, kT * kB), 256, PJSMEM>>>(
        pg, pbe, pm, pva, pb, x, out);
}